// round 16
// baseline (speedup 1.0000x reference)
#include <cuda_runtime.h>

#define H 1024
#define V 50257
// First PREFIX_ROWS of W_out are loaded with default policy -> persist in L2
// across graph replays (64 MB). 48 MB GRU weights + 64 MB prefix = 112 MB < 126 MB L2.
#define PREFIX_ROWS 16384

// ---------------- scratch (no allocation allowed) ----------------
__device__ float g_gi0[3 * H];
__device__ float g_gh0[3 * H];
__device__ float g_gh1[3 * H];
__device__ float g_x1[H];     // h_new layer0 (input to layer1)
__device__ float g_x2[H];     // h_new layer1 (input to out_proj)
__device__ float g_sumexp;

__device__ __forceinline__ float dot4(float4 a, float4 b) {
    return a.x * b.x + a.y * b.y + a.z * b.z + a.w * b.w;
}

__device__ __forceinline__ float warp_sum(float a) {
    #pragma unroll
    for (int off = 16; off > 0; off >>= 1)
        a += __shfl_down_sync(0xffffffffu, a, off);
    return a;
}

__device__ __forceinline__ float sigmoidf(float x) {
    return 1.0f / (1.0f + expf(-x));
}

// ============ K1: fused matvec x3 (36 MB, L2-persistent across replays) ============
// job 0: gi0 = W_ih[0] @ relu(emb[tok])
// job 1: gh0 = W_hh[0] @ hidden[0]
// job 2: gh1 = W_hh[1] @ hidden[1]
// warp-per-row, 8 warps/block, 384 blocks per job -> grid 1152.
__global__ void __launch_bounds__(256) mv3_kernel(
    const long long* __restrict__ tok,
    const float* __restrict__ hidden,
    const float* __restrict__ emb,
    const float* __restrict__ Wih,
    const float* __restrict__ Whh)
{
    __shared__ float4 sv[H / 4];
    int bid = blockIdx.x;
    int job = bid / 384;
    int t = threadIdx.x;

    if (bid == 0 && t == 0) g_sumexp = 0.0f;   // reset for this replay

    const float* W;
    float* out;
    if (job == 0)      { W = Wih;                       out = g_gi0; }
    else if (job == 1) { W = Whh;                       out = g_gh0; }
    else               { W = Whh + (size_t)3 * H * H;   out = g_gh1; }

    if (job == 0) {
        long long tk = tok[0];
        float4 e = ((const float4*)(emb + tk * (long long)H))[t];
        e.x = fmaxf(e.x, 0.0f); e.y = fmaxf(e.y, 0.0f);
        e.z = fmaxf(e.z, 0.0f); e.w = fmaxf(e.w, 0.0f);
        sv[t] = e;
    } else {
        sv[t] = ((const float4*)(hidden + (job - 1) * H))[t];
    }
    __syncthreads();

    int warp = t >> 5, lane = t & 31;
    int r = (bid % 384) * 8 + warp;
    const float4* wr = (const float4*)(W + (size_t)r * H);

    float acc = 0.0f;
    #pragma unroll
    for (int k = 0; k < 8; k++) {
        int idx = lane + 32 * k;
        acc += dot4(wr[idx], sv[idx]);       // default policy -> L2-persistent
    }
    acc = warp_sum(acc);
    if (lane == 0) out[r] = acc;
}

// ============ K2: gates layer 0 (tiny, L2-resident) [PDL, grid 4] ============
__global__ void __launch_bounds__(256) gates0_kernel(
    const float* __restrict__ hidden,
    const float* __restrict__ bih,
    const float* __restrict__ bhh,
    float* __restrict__ d_out)
{
    int j = blockIdx.x * 256 + threadIdx.x;
    float b0 = bih[j], b1 = bih[H + j], b2 = bih[2 * H + j];
    float c0 = bhh[j], c1 = bhh[H + j], c2 = bhh[2 * H + j];
    float h  = hidden[j];

    cudaGridDependencySynchronize();

    float r = sigmoidf((g_gi0[j] + b0)     + (g_gh0[j] + c0));
    float z = sigmoidf((g_gi0[H + j] + b1) + (g_gh0[H + j] + c1));
    float n = tanhf((g_gi0[2 * H + j] + b2) + r * (g_gh0[2 * H + j] + c2));
    float hn = (1.0f - z) * n + z * h;

    g_x1[j] = hn;
    d_out[V + j] = hn;
}

// ============ K3: layer-1 gi matvec (12 MB, L2-resident) fused with gates ============
// block j computes output element j; 262K threads, 3 loads each.
__global__ void __launch_bounds__(256) gru1_kernel(
    const float* __restrict__ hidden,
    const float* __restrict__ Wih1,     // W_ih + 3H*H
    const float* __restrict__ bih1,     // b_ih + 3H
    const float* __restrict__ bhh1,     // b_hh + 3H
    float* __restrict__ d_out)
{
    __shared__ float4 sx[H / 4];
    __shared__ float sred[8][3];
    int t = threadIdx.x;
    sx[t] = ((const float4*)g_x1)[t];
    __syncthreads();

    int j = blockIdx.x;
    const float4* w0 = (const float4*)(Wih1 + (size_t)j * H);
    const float4* w1 = (const float4*)(Wih1 + (size_t)(H + j) * H);
    const float4* w2 = (const float4*)(Wih1 + (size_t)(2 * H + j) * H);

    float4 xv = sx[t];
    float a0 = dot4(w0[t], xv);              // default policy -> L2-persistent
    float a1 = dot4(w1[t], xv);
    float a2 = dot4(w2[t], xv);

    a0 = warp_sum(a0); a1 = warp_sum(a1); a2 = warp_sum(a2);
    int w = t >> 5, lane = t & 31;
    if (lane == 0) { sred[w][0] = a0; sred[w][1] = a1; sred[w][2] = a2; }
    __syncthreads();

    if (t == 0) {
        float s0 = 0.f, s1 = 0.f, s2 = 0.f;
        #pragma unroll
        for (int k = 0; k < 8; k++) { s0 += sred[k][0]; s1 += sred[k][1]; s2 += sred[k][2]; }

        float gi_r = s0 + bih1[j];
        float gi_z = s1 + bih1[H + j];
        float gi_n = s2 + bih1[2 * H + j];
        float gh_r = g_gh1[j]         + bhh1[j];
        float gh_z = g_gh1[H + j]     + bhh1[H + j];
        float gh_n = g_gh1[2 * H + j] + bhh1[2 * H + j];

        float r = sigmoidf(gi_r + gh_r);
        float z = sigmoidf(gi_z + gh_z);
        float n = tanhf(gi_n + r * gh_n);
        float h = hidden[H + j];
        float hn = (1.0f - z) * n + z * h;

        g_x2[j] = hn;
        d_out[V + H + j] = hn;
    }
}

// ============ K4: output projection + fused sum-exp ============
// 1 row per warp, 8 warps per block, grid 6283.
// Rows < PREFIX_ROWS: default-policy loads -> 64 MB persists in L2 across
// replays (hits on every timed replay). Rows >= PREFIX_ROWS: __ldcs stream
// (evict-first; protects both resident sets). Steady-state DRAM demand: 142 MB.
__global__ void __launch_bounds__(256) out_proj_kernel(
    const float* __restrict__ W,
    const float* __restrict__ b,
    float* __restrict__ d_out)
{
    __shared__ float4 sx[H / 4];
    __shared__ float sexp[8];
    int t = threadIdx.x;
    sx[t] = ((const float4*)g_x2)[t];
    __syncthreads();

    int warp = t >> 5, lane = t & 31;
    int row = blockIdx.x * 8 + warp;
    bool valid = row < V;
    size_t r = valid ? (size_t)row : 0;

    const float4* wr = (const float4*)(W + r * H);
    float acc = 0.0f;
    if (row < PREFIX_ROWS) {
        #pragma unroll
        for (int k = 0; k < 8; k++) {
            int idx = lane + 32 * k;
            float4 w4 = wr[idx];             // default policy -> L2-persistent prefix
            float4 x4 = sx[idx];
            acc += w4.x * x4.x + w4.y * x4.y + w4.z * x4.z + w4.w * x4.w;
        }
    } else {
        #pragma unroll
        for (int k = 0; k < 8; k++) {
            int idx = lane + 32 * k;
            float4 w4 = __ldcs(&wr[idx]);    // evict-first stream
            float4 x4 = sx[idx];
            acc += w4.x * x4.x + w4.y * x4.y + w4.z * x4.z + w4.w * x4.w;
        }
    }
    acc = warp_sum(acc);

    if (lane == 0) {
        float e = 0.0f;
        if (valid) {
            float lg = acc + b[r];
            d_out[r] = lg;
            e = expf(lg);
        }
        sexp[warp] = e;
    }
    __syncthreads();
    if (t == 0) {
        float s = 0.0f;
        #pragma unroll
        for (int k = 0; k < 8; k++) s += sexp[k];
        atomicAdd(&g_sumexp, s);
    }
}

// ============ K5: finalize logprobs (float4 in-place) [PDL, zero pre-sync traffic] ============
__global__ void __launch_bounds__(256) finalize_kernel(float* __restrict__ d_out) {
    int i4 = blockIdx.x * 256 + threadIdx.x;   // float4 index

    cudaGridDependencySynchronize();

    float lse = logf(g_sumexp);
    if (i4 < V / 4) {                          // V/4 = 12564
        float4 v = ((float4*)d_out)[i4];
        v.x -= lse; v.y -= lse; v.z -= lse; v.w -= lse;
        ((float4*)d_out)[i4] = v;
    } else if (i4 == V / 4) {                  // tail element (V = 4*12564 + 1)
        d_out[V - 1] -= lse;
    }
}

// ---------------- launch helpers ----------------
template <typename... Args>
static void launch_pdl(void (*kern)(Args...), dim3 grid, dim3 block, Args... args) {
    cudaLaunchConfig_t cfg = {};
    cfg.gridDim = grid;
    cfg.blockDim = block;
    cfg.dynamicSmemBytes = 0;
    cfg.stream = 0;
    cudaLaunchAttribute attr;
    attr.id = cudaLaunchAttributeProgrammaticStreamSerialization;
    attr.val.programmaticStreamSerializationAllowed = 1;
    cfg.attrs = &attr;
    cfg.numAttrs = 1;
    cudaLaunchKernelEx(&cfg, kern, args...);
}

extern "C" void kernel_launch(void* const* d_in, const int* in_sizes, int n_in,
                              void* d_out, int out_size) {
    const long long* tok  = (const long long*)d_in[0];
    const float* hidden   = (const float*)d_in[1];
    const float* emb      = (const float*)d_in[2];
    const float* W_ih     = (const float*)d_in[3];
    const float* W_hh     = (const float*)d_in[4];
    const float* b_ih     = (const float*)d_in[5];
    const float* b_hh     = (const float*)d_in[6];
    const float* W_out    = (const float*)d_in[7];
    const float* b_out    = (const float*)d_in[8];
    float* out = (float*)d_out;

    mv3_kernel<<<1152, 256>>>(tok, hidden, emb, W_ih, W_hh);

    launch_pdl(gates0_kernel, dim3(4), dim3(256),
               hidden, b_ih, b_hh, out);

    gru1_kernel<<<H, 256>>>(hidden,
                            W_ih + (size_t)3 * H * H,
                            b_ih + 3 * H,
                            b_hh + 3 * H,
                            out);

    out_proj_kernel<<<(V + 7) / 8, 256>>>(W_out, b_out, out);

    launch_pdl(finalize_kernel, dim3((V / 4 + 256) / 256), dim3(256), out);
}

// round 17
// speedup vs baseline: 1.2764x; 1.2764x over previous
#include <cuda_runtime.h>

#define H 1024
#define V 50257
// First PREFIX_ROWS of W_out loaded with ld.global.cg (L2 default priority,
// no L1 allocation) -> 32 MB persists in L2 across graph replays.
// Resident budget: 48 MB GRU weights + 32 MB prefix = 80 MB (63% of 126 MB L2).
// R16 showed 112 MB (89%) thrashes; R10 showed 48 MB (38%) persists.
#define PREFIX_ROWS 8192

// ---------------- scratch (no allocation allowed) ----------------
__device__ float g_gi0[3 * H];
__device__ float g_gh0[3 * H];
__device__ float g_gh1[3 * H];
__device__ float g_x1[H];     // h_new layer0 (input to layer1)
__device__ float g_x2[H];     // h_new layer1 (input to out_proj)
__device__ float g_sumexp;

__device__ __forceinline__ float dot4(float4 a, float4 b) {
    return a.x * b.x + a.y * b.y + a.z * b.z + a.w * b.w;
}

__device__ __forceinline__ float warp_sum(float a) {
    #pragma unroll
    for (int off = 16; off > 0; off >>= 1)
        a += __shfl_down_sync(0xffffffffu, a, off);
    return a;
}

__device__ __forceinline__ float sigmoidf(float x) {
    return 1.0f / (1.0f + expf(-x));
}

// ============ K1: fused matvec x3 (36 MB, L2-persistent across replays) ============
// job 0: gi0 = W_ih[0] @ relu(emb[tok])
// job 1: gh0 = W_hh[0] @ hidden[0]
// job 2: gh1 = W_hh[1] @ hidden[1]
// warp-per-row, 8 warps/block, 384 blocks per job -> grid 1152.
__global__ void __launch_bounds__(256) mv3_kernel(
    const long long* __restrict__ tok,
    const float* __restrict__ hidden,
    const float* __restrict__ emb,
    const float* __restrict__ Wih,
    const float* __restrict__ Whh)
{
    __shared__ float4 sv[H / 4];
    int bid = blockIdx.x;
    int job = bid / 384;
    int t = threadIdx.x;

    if (bid == 0 && t == 0) g_sumexp = 0.0f;   // reset for this replay

    const float* W;
    float* out;
    if (job == 0)      { W = Wih;                       out = g_gi0; }
    else if (job == 1) { W = Whh;                       out = g_gh0; }
    else               { W = Whh + (size_t)3 * H * H;   out = g_gh1; }

    if (job == 0) {
        long long tk = tok[0];
        float4 e = ((const float4*)(emb + tk * (long long)H))[t];
        e.x = fmaxf(e.x, 0.0f); e.y = fmaxf(e.y, 0.0f);
        e.z = fmaxf(e.z, 0.0f); e.w = fmaxf(e.w, 0.0f);
        sv[t] = e;
    } else {
        sv[t] = ((const float4*)(hidden + (job - 1) * H))[t];
    }
    __syncthreads();

    int warp = t >> 5, lane = t & 31;
    int r = (bid % 384) * 8 + warp;
    const float4* wr = (const float4*)(W + (size_t)r * H);

    float acc = 0.0f;
    #pragma unroll
    for (int k = 0; k < 8; k++) {
        int idx = lane + 32 * k;
        acc += dot4(wr[idx], sv[idx]);       // default policy -> L2-persistent
    }
    acc = warp_sum(acc);
    if (lane == 0) out[r] = acc;
}

// ============ K2: gates layer 0 (tiny, L2-resident) [PDL, grid 4] ============
__global__ void __launch_bounds__(256) gates0_kernel(
    const float* __restrict__ hidden,
    const float* __restrict__ bih,
    const float* __restrict__ bhh,
    float* __restrict__ d_out)
{
    int j = blockIdx.x * 256 + threadIdx.x;
    float b0 = bih[j], b1 = bih[H + j], b2 = bih[2 * H + j];
    float c0 = bhh[j], c1 = bhh[H + j], c2 = bhh[2 * H + j];
    float h  = hidden[j];

    cudaGridDependencySynchronize();

    float r = sigmoidf((g_gi0[j] + b0)     + (g_gh0[j] + c0));
    float z = sigmoidf((g_gi0[H + j] + b1) + (g_gh0[H + j] + c1));
    float n = tanhf((g_gi0[2 * H + j] + b2) + r * (g_gh0[2 * H + j] + c2));
    float hn = (1.0f - z) * n + z * h;

    g_x1[j] = hn;
    d_out[V + j] = hn;
}

// ============ K3: layer-1 gi matvec (12 MB, L2-resident) fused with gates ============
// block j computes output element j; 262K threads, 3 loads each.
__global__ void __launch_bounds__(256) gru1_kernel(
    const float* __restrict__ hidden,
    const float* __restrict__ Wih1,     // W_ih + 3H*H
    const float* __restrict__ bih1,     // b_ih + 3H
    const float* __restrict__ bhh1,     // b_hh + 3H
    float* __restrict__ d_out)
{
    __shared__ float4 sx[H / 4];
    __shared__ float sred[8][3];
    int t = threadIdx.x;
    sx[t] = ((const float4*)g_x1)[t];
    __syncthreads();

    int j = blockIdx.x;
    const float4* w0 = (const float4*)(Wih1 + (size_t)j * H);
    const float4* w1 = (const float4*)(Wih1 + (size_t)(H + j) * H);
    const float4* w2 = (const float4*)(Wih1 + (size_t)(2 * H + j) * H);

    float4 xv = sx[t];
    float a0 = dot4(w0[t], xv);              // default policy -> L2-persistent
    float a1 = dot4(w1[t], xv);
    float a2 = dot4(w2[t], xv);

    a0 = warp_sum(a0); a1 = warp_sum(a1); a2 = warp_sum(a2);
    int w = t >> 5, lane = t & 31;
    if (lane == 0) { sred[w][0] = a0; sred[w][1] = a1; sred[w][2] = a2; }
    __syncthreads();

    if (t == 0) {
        float s0 = 0.f, s1 = 0.f, s2 = 0.f;
        #pragma unroll
        for (int k = 0; k < 8; k++) { s0 += sred[k][0]; s1 += sred[k][1]; s2 += sred[k][2]; }

        float gi_r = s0 + bih1[j];
        float gi_z = s1 + bih1[H + j];
        float gi_n = s2 + bih1[2 * H + j];
        float gh_r = g_gh1[j]         + bhh1[j];
        float gh_z = g_gh1[H + j]     + bhh1[H + j];
        float gh_n = g_gh1[2 * H + j] + bhh1[2 * H + j];

        float r = sigmoidf(gi_r + gh_r);
        float z = sigmoidf(gi_z + gh_z);
        float n = tanhf(gi_n + r * gh_n);
        float h = hidden[H + j];
        float hn = (1.0f - z) * n + z * h;

        g_x2[j] = hn;
        d_out[V + H + j] = hn;
    }
}

// ============ K4: output projection + fused sum-exp ============
// 1 row per warp, 8 warps per block, grid 6283.
// Rows < PREFIX_ROWS: __ldcg (L2-cached, L1-bypass) -> 32 MB persists across
// replays. Rows >= PREFIX_ROWS: __ldcs stream (evict-first; protects the
// resident sets). Steady-state DRAM demand: 174 MB.
__global__ void __launch_bounds__(256) out_proj_kernel(
    const float* __restrict__ W,
    const float* __restrict__ b,
    float* __restrict__ d_out)
{
    __shared__ float4 sx[H / 4];
    __shared__ float sexp[8];
    int t = threadIdx.x;
    sx[t] = ((const float4*)g_x2)[t];
    __syncthreads();

    int warp = t >> 5, lane = t & 31;
    int row = blockIdx.x * 8 + warp;
    bool valid = row < V;
    size_t r = valid ? (size_t)row : 0;

    const float4* wr = (const float4*)(W + r * H);
    float acc = 0.0f;
    if (row < PREFIX_ROWS) {
        #pragma unroll
        for (int k = 0; k < 8; k++) {
            int idx = lane + 32 * k;
            float4 w4 = __ldcg(&wr[idx]);    // L2 default priority, no L1 alloc
            float4 x4 = sx[idx];
            acc += w4.x * x4.x + w4.y * x4.y + w4.z * x4.z + w4.w * x4.w;
        }
    } else {
        #pragma unroll
        for (int k = 0; k < 8; k++) {
            int idx = lane + 32 * k;
            float4 w4 = __ldcs(&wr[idx]);    // evict-first stream
            float4 x4 = sx[idx];
            acc += w4.x * x4.x + w4.y * x4.y + w4.z * x4.z + w4.w * x4.w;
        }
    }
    acc = warp_sum(acc);

    if (lane == 0) {
        float e = 0.0f;
        if (valid) {
            float lg = acc + b[r];
            d_out[r] = lg;
            e = expf(lg);
        }
        sexp[warp] = e;
    }
    __syncthreads();
    if (t == 0) {
        float s = 0.0f;
        #pragma unroll
        for (int k = 0; k < 8; k++) s += sexp[k];
        atomicAdd(&g_sumexp, s);
    }
}

// ============ K5: finalize logprobs (float4 in-place) [PDL, zero pre-sync traffic] ============
__global__ void __launch_bounds__(256) finalize_kernel(float* __restrict__ d_out) {
    int i4 = blockIdx.x * 256 + threadIdx.x;   // float4 index

    cudaGridDependencySynchronize();

    float lse = logf(g_sumexp);
    if (i4 < V / 4) {                          // V/4 = 12564
        float4 v = ((float4*)d_out)[i4];
        v.x -= lse; v.y -= lse; v.z -= lse; v.w -= lse;
        ((float4*)d_out)[i4] = v;
    } else if (i4 == V / 4) {                  // tail element (V = 4*12564 + 1)
        d_out[V - 1] -= lse;
    }
}

// ---------------- launch helpers ----------------
template <typename... Args>
static void launch_pdl(void (*kern)(Args...), dim3 grid, dim3 block, Args... args) {
    cudaLaunchConfig_t cfg = {};
    cfg.gridDim = grid;
    cfg.blockDim = block;
    cfg.dynamicSmemBytes = 0;
    cfg.stream = 0;
    cudaLaunchAttribute attr;
    attr.id = cudaLaunchAttributeProgrammaticStreamSerialization;
    attr.val.programmaticStreamSerializationAllowed = 1;
    cfg.attrs = &attr;
    cfg.numAttrs = 1;
    cudaLaunchKernelEx(&cfg, kern, args...);
}

extern "C" void kernel_launch(void* const* d_in, const int* in_sizes, int n_in,
                              void* d_out, int out_size) {
    const long long* tok  = (const long long*)d_in[0];
    const float* hidden   = (const float*)d_in[1];
    const float* emb      = (const float*)d_in[2];
    const float* W_ih     = (const float*)d_in[3];
    const float* W_hh     = (const float*)d_in[4];
    const float* b_ih     = (const float*)d_in[5];
    const float* b_hh     = (const float*)d_in[6];
    const float* W_out    = (const float*)d_in[7];
    const float* b_out    = (const float*)d_in[8];
    float* out = (float*)d_out;

    mv3_kernel<<<1152, 256>>>(tok, hidden, emb, W_ih, W_hh);

    launch_pdl(gates0_kernel, dim3(4), dim3(256),
               hidden, b_ih, b_hh, out);

    gru1_kernel<<<H, 256>>>(hidden,
                            W_ih + (size_t)3 * H * H,
                            b_ih + 3 * H,
                            b_hh + 3 * H,
                            out);

    out_proj_kernel<<<(V + 7) / 8, 256>>>(W_out, b_out, out);

    launch_pdl(finalize_kernel, dim3((V / 4 + 256) / 256), dim3(256), out);
}